// round 17
// baseline (speedup 1.0000x reference)
#include <cuda_runtime.h>
#include <cuda_fp16.h>
#include <math.h>
#include <stdint.h>

// ---------------------------------------------------------------------------
// MoE: router -> scatter -> fp16 mma.sync grouped GEMM1(gelu) -> GEMM2(+fused
// atomic combine) . R13: combine folded into GEMM2 epilogue via atomicAdd
// (exactly 2 commutative adds per output element -> deterministic).
// ---------------------------------------------------------------------------
#define DD    1024
#define HH    4096
#define EE    8
#define NTOK  8192
#define BMT   128
#define MAXROWS (NTOK*2 + EE*BMT)   // 17408
#define BKH   64                    // K halves per chunk (128B rows, SW128)
#define NT    128                   // N cols per block

// stage: A 16K | B 16K = 32KB, 3 stages = 96KB -> 2 CTAs/SM
#define OFF_A   0
#define OFF_B   16384
#define STAGE   32768
#define NSTG    3
#define GEMM_SMEM (NSTG*STAGE)

// -------- scratch (device globals) -----------------------------------------
__device__ int   g_counts[EE];
__device__ int   g_cursor[EE];
__device__ int   g_off[EE + 1];
__device__ int   g_total;
__device__ int   g_tok[MAXROWS];
__device__ float g_ps[MAXROWS];     // slot -> gate prob
__device__ int   g_idx[NTOK * 2];
__device__ float g_p[NTOK * 2];

__device__ __align__(256) __half g_w1h[(size_t)EE * HH * DD];  // fp16(W1^T) [E][H][D]
__device__ __align__(256) __half g_w2h[(size_t)EE * DD * HH];  // fp16(W2^T) [E][D][H]
__device__ __align__(256) __half g_ah[(size_t)MAXROWS * DD];   // gathered fp16(x)
__device__ __align__(256) __half g_hh[(size_t)MAXROWS * HH];   // fp16(gelu(h))

// -------- PTX helpers -------------------------------------------------------
__device__ __forceinline__ uint32_t smem_u32(const void* p) {
    uint32_t a;
    asm("{ .reg .u64 t; cvta.to.shared.u64 t, %1; cvt.u32.u64 %0, t; }"
        : "=r"(a) : "l"(p));
    return a;
}

#define CP_A16(dst, src) \
    asm volatile("cp.async.cg.shared.global [%0], [%1], 16;" \
                 :: "r"(dst), "l"(src))
#define CP_COMMIT() asm volatile("cp.async.commit_group;" ::: "memory")
#define CP_WAIT1()  asm volatile("cp.async.wait_group 1;" ::: "memory")
#define CP_WAIT0()  asm volatile("cp.async.wait_group 0;" ::: "memory")

#define LDSM4(r0, r1, r2, r3, addr) \
    asm volatile("ldmatrix.sync.aligned.m8n8.x4.shared.b16 {%0,%1,%2,%3}, [%4];" \
                 : "=r"(r0), "=r"(r1), "=r"(r2), "=r"(r3) : "r"(addr))

#define HMMA(c, a, b) \
    asm volatile("mma.sync.aligned.m16n8k16.row.col.f32.f16.f16.f32 " \
                 "{%0,%1,%2,%3}, {%4,%5,%6,%7}, {%8,%9}, {%0,%1,%2,%3};" \
                 : "+f"((c)[0]), "+f"((c)[1]), "+f"((c)[2]), "+f"((c)[3]) \
                 : "r"((a)[0]), "r"((a)[1]), "r"((a)[2]), "r"((a)[3]), \
                   "r"((b)[0]), "r"((b)[1]))

// -------- small kernels ----------------------------------------------------
__global__ void init_k() {
    int i = blockIdx.x * blockDim.x + threadIdx.x;
    if (i < EE) g_counts[i] = 0;
    if (i < MAXROWS) g_tok[i] = 0;
}

__global__ void zero_out_k(float4* __restrict__ out) {
    out[blockIdx.x * blockDim.x + threadIdx.x] = make_float4(0.f, 0.f, 0.f, 0.f);
}

__global__ void router_k(const float* __restrict__ x,
                         const float* __restrict__ Wg,
                         const float* __restrict__ bg) {
    int warp = (blockIdx.x * blockDim.x + threadIdx.x) >> 5;
    int lane = threadIdx.x & 31;
    if (warp >= NTOK) return;
    const float* xr = x + (size_t)warp * DD;
    float acc[EE];
#pragma unroll
    for (int e = 0; e < EE; e++) acc[e] = 0.f;
#pragma unroll
    for (int i = 0; i < DD / 32; i++) {
        float xv = xr[lane + 32 * i];
        const float* wr = Wg + (size_t)(lane + 32 * i) * EE;
#pragma unroll
        for (int e = 0; e < EE; e++) acc[e] += xv * wr[e];
    }
#pragma unroll
    for (int e = 0; e < EE; e++)
#pragma unroll
        for (int o = 16; o > 0; o >>= 1)
            acc[e] += __shfl_xor_sync(0xffffffffu, acc[e], o);
    if (lane == 0) {
        float l[EE];
        float m = -1e30f;
#pragma unroll
        for (int e = 0; e < EE; e++) { l[e] = acc[e] + bg[e]; m = fmaxf(m, l[e]); }
        float s = 0.f;
#pragma unroll
        for (int e = 0; e < EE; e++) s += expf(l[e] - m);
        int i0 = 0;
#pragma unroll
        for (int e = 1; e < EE; e++) if (l[e] > l[i0]) i0 = e;
        int i1 = (i0 == 0) ? 1 : 0;
#pragma unroll
        for (int e = 0; e < EE; e++) if (e != i0 && l[e] > l[i1]) i1 = e;
        g_idx[warp * 2 + 0] = i0;  g_p[warp * 2 + 0] = expf(l[i0] - m) / s;
        g_idx[warp * 2 + 1] = i1;  g_p[warp * 2 + 1] = expf(l[i1] - m) / s;
        atomicAdd(&g_counts[i0], 1);
        atomicAdd(&g_counts[i1], 1);
    }
}

__global__ void scan_k() {
    if (threadIdx.x == 0) {
        int off = 0;
        for (int e = 0; e < EE; e++) {
            g_off[e] = off;
            g_cursor[e] = off;
            off += (g_counts[e] + BMT - 1) / BMT * BMT;
        }
        g_off[EE] = off;
        g_total = off;
    }
}

__global__ void scatter_k() {
    int n = blockIdx.x * blockDim.x + threadIdx.x;
    if (n >= NTOK) return;
#pragma unroll
    for (int k = 0; k < 2; k++) {
        int e = g_idx[n * 2 + k];
        int pos = atomicAdd(&g_cursor[e], 1);
        g_tok[pos] = n;
        g_ps[pos] = g_p[n * 2 + k];
    }
}

// gather x rows per slot -> fp16
__global__ void pregather_k(const float* __restrict__ x) {
    int row = blockIdx.x, tid = threadIdx.x;
    int tok = g_tok[row];
    float4 v = ((const float4*)(x + (size_t)tok * DD))[tid];
    __half2 a; a.x = __float2half(v.x); a.y = __float2half(v.y);
    __half2 b; b.x = __float2half(v.z); b.y = __float2half(v.w);
    ((uint2*)(g_ah + (size_t)row * DD))[tid] =
        make_uint2(*(uint32_t*)&a, *(uint32_t*)&b);
}

// transpose in[e][R][C] fp32 -> out[e][C][R] fp16
__global__ void transconv_k(const float* __restrict__ in,
                            __half* __restrict__ oh,
                            int R, int C) {
    __shared__ float t[32][33];
    int e = blockIdx.z;
    const float* ip = in + (size_t)e * R * C;
    size_t ob = (size_t)e * R * C;
    int c0 = blockIdx.x * 32, r0 = blockIdx.y * 32;
#pragma unroll
    for (int i = threadIdx.y; i < 32; i += 8)
        t[i][threadIdx.x] = ip[(size_t)(r0 + i) * C + c0 + threadIdx.x];
    __syncthreads();
#pragma unroll
    for (int i = threadIdx.y; i < 32; i += 8) {
        size_t o = ob + (size_t)(c0 + i) * R + r0 + threadIdx.x;
        oh[o] = __float2half(t[threadIdx.x][i]);
    }
}

// ---------------------------------------------------------------------------
// fp16 mma.sync grouped GEMM.  C[128 x 128] per block, 128 threads, 2 CTA/SM.
// 4 warps: warp_m in {0,1} (64 rows), warp_n in {0,1} (64 cols). Warp 64x64.
// MODE 1: A=g_ah, out->g_hh (bias+gelu, fp16)
// MODE 2: A=g_hh, fused combine: out[tok] += p_slot * (acc + bias)  (atomicAdd)
// ---------------------------------------------------------------------------
template <int KDIM>
__device__ __forceinline__ void load_stage(
    uint32_t stu,
    const __half* __restrict__ Ap, const __half* __restrict__ Bp,
    int kof, int tid) {
#pragma unroll
    for (int it = 0; it < 8; ++it) {
        int idx = it * 128 + tid;
        int r = idx >> 3, c = idx & 7;
        uint32_t d = (uint32_t)(r * 128 + ((c ^ (r & 7)) << 4));
        CP_A16(stu + OFF_A + d, Ap + (size_t)r * KDIM + kof + c * 8);
    }
#pragma unroll
    for (int it = 0; it < 8; ++it) {
        int idx = it * 128 + tid;
        int r = idx >> 3, c = idx & 7;
        uint32_t d = (uint32_t)(r * 128 + ((c ^ (r & 7)) << 4));
        CP_A16(stu + OFF_B + d, Bp + (size_t)r * KDIM + kof + c * 8);
    }
}

template <int KDIM, int NDIM, int MODE>
__global__ __launch_bounds__(128, 2)
void gemm_hmma(const __half* __restrict__ A, const __half* __restrict__ B,
               const float* __restrict__ bias, float* __restrict__ outp) {
    const int row0 = blockIdx.y * BMT;
    if (row0 >= g_total) return;
    int e = 0;
    while (row0 >= g_off[e + 1]) ++e;
    const int nbase = blockIdx.x * NT;

    extern __shared__ __align__(128) char dsmem[];
    const uint32_t smem_u = smem_u32(dsmem);

    const int tid = threadIdx.x;
    const int lane = tid & 31;
    const int wid = tid >> 5;
    const int warp_m = wid & 1;   // 2 warps in M (64 rows each)
    const int warp_n = wid >> 1;  // 2 warps in N (64 cols each)

    const __half* Ap = A + (size_t)row0 * KDIM;
    const __half* Bp = B + ((size_t)e * NDIM + nbase) * KDIM;

    constexpr int NC = KDIM / BKH;

    // prologue: stages 0,1
#pragma unroll
    for (int p = 0; p < NSTG - 1; ++p) {
        load_stage<KDIM>(smem_u + p * STAGE, Ap, Bp, p * BKH, tid);
        CP_COMMIT();
    }

    float acc[4][8][4] = {};

    for (int kc = 0; kc < NC; ++kc) {
        if (NC - 1 - kc >= 1) CP_WAIT1(); else CP_WAIT0();
        __syncthreads();   // stage kc ready AND stage kc-1 reads done

        if (kc + NSTG - 1 < NC) {
            load_stage<KDIM>(smem_u + ((kc + NSTG - 1) % NSTG) * STAGE,
                             Ap, Bp, (kc + NSTG - 1) * BKH, tid);
            CP_COMMIT();
        }

        const uint32_t stu = smem_u + (kc % NSTG) * STAGE;
#pragma unroll
        for (int ks = 0; ks < 4; ++ks) {          // 4 x k16 within BK=64
            uint32_t a[4][4], b[8][2];
#pragma unroll
            for (int mi = 0; mi < 4; ++mi) {      // 4 m16 tiles over 64 rows
                int tile = lane >> 3;
                int row = warp_m * 64 + mi * 16 + (lane & 7) + ((tile & 1) << 3);
                int kc8 = ks * 2 + (tile >> 1);
                uint32_t off = (uint32_t)(row * 128 + ((kc8 ^ (row & 7)) << 4));
                LDSM4(a[mi][0], a[mi][1], a[mi][2], a[mi][3], stu + OFF_A + off);
            }
#pragma unroll
            for (int ng = 0; ng < 4; ++ng) {      // 8 n8 tiles over 64 cols
                int row = warp_n * 64 + ng * 16 + ((lane >> 4) << 3) + (lane & 7);
                int kc8 = ks * 2 + ((lane >> 3) & 1);
                uint32_t off = (uint32_t)(row * 128 + ((kc8 ^ (row & 7)) << 4));
                LDSM4(b[2 * ng][0], b[2 * ng][1], b[2 * ng + 1][0], b[2 * ng + 1][1],
                      stu + OFF_B + off);
            }
#pragma unroll
            for (int mi = 0; mi < 4; ++mi)
#pragma unroll
                for (int nt = 0; nt < 8; ++nt) HMMA(acc[mi][nt], a[mi], b[nt]);
        }
        __syncthreads();
    }

    // epilogue
    const int gr = lane >> 2;
    const int gc = (lane & 3) * 2;
    const int ve = (MODE == 2) ? (g_off[e] + g_counts[e]) : 0;  // valid slot end
#pragma unroll
    for (int mi = 0; mi < 4; ++mi) {
#pragma unroll
        for (int h = 0; h < 2; ++h) {
            const int r = row0 + warp_m * 64 + mi * 16 + gr + h * 8;  // slot row
            if (MODE == 1) {
#pragma unroll
                for (int nt = 0; nt < 8; ++nt) {
                    const int col = nbase + warp_n * 64 + nt * 8 + gc;
                    const float2 bv = *(const float2*)(bias + (size_t)e * NDIM + col);
                    float u0 = acc[mi][nt][2 * h]     + bv.x;
                    float u1 = acc[mi][nt][2 * h + 1] + bv.y;
                    u0 = 0.5f * u0 * (1.f + erff(u0 * 0.70710678118654752f));
                    u1 = 0.5f * u1 * (1.f + erff(u1 * 0.70710678118654752f));
                    __half2 hv; hv.x = __float2half(u0); hv.y = __float2half(u1);
                    *(__half2*)(g_hh + (size_t)r * HH + col) = hv;
                }
            } else {
                if (r < ve) {                      // skip padding slots
                    const int   tok = g_tok[r];
                    const float p   = g_ps[r];
                    float* orow = outp + (size_t)tok * NDIM;
#pragma unroll
                    for (int nt = 0; nt < 8; ++nt) {
                        const int col = nbase + warp_n * 64 + nt * 8 + gc;
                        const float2 bv = *(const float2*)(bias + (size_t)e * NDIM + col);
                        atomicAdd(orow + col,     p * (acc[mi][nt][2 * h]     + bv.x));
                        atomicAdd(orow + col + 1, p * (acc[mi][nt][2 * h + 1] + bv.y));
                    }
                }
            }
        }
    }
}

// ---------------------------------------------------------------------------
extern "C" void kernel_launch(void* const* d_in, const int* in_sizes, int n_in,
                              void* d_out, int out_size) {
    const float* x  = (const float*)d_in[0];
    const float* Wg = (const float*)d_in[1];
    const float* bg = (const float*)d_in[2];
    const float* W1 = (const float*)d_in[3];
    const float* b1 = (const float*)d_in[4];
    const float* W2 = (const float*)d_in[5];
    const float* b2 = (const float*)d_in[6];
    float* out = (float*)d_out;

    cudaFuncSetAttribute(gemm_hmma<DD, HH, 1>,
                         cudaFuncAttributeMaxDynamicSharedMemorySize, GEMM_SMEM);
    cudaFuncSetAttribute(gemm_hmma<HH, DD, 2>,
                         cudaFuncAttributeMaxDynamicSharedMemorySize, GEMM_SMEM);

    __half *w1h, *w2h, *ah, *hh;
    cudaGetSymbolAddress((void**)&w1h, g_w1h);
    cudaGetSymbolAddress((void**)&w2h, g_w2h);
    cudaGetSymbolAddress((void**)&ah,  g_ah);
    cudaGetSymbolAddress((void**)&hh,  g_hh);

    init_k<<<MAXROWS / 256, 256>>>();
    zero_out_k<<<(NTOK * DD / 4) / 256, 256>>>((float4*)out);
    router_k<<<NTOK / 8, 256>>>(x, Wg, bg);
    scan_k<<<1, 32>>>();
    scatter_k<<<NTOK / 256, 256>>>();
    pregather_k<<<MAXROWS, 256>>>(x);
    // W1[e][D][H] -> [e][H][D] ; W2[e][H][D] -> [e][D][H]
    transconv_k<<<dim3(HH / 32, DD / 32, EE), dim3(32, 8)>>>(W1, w1h, DD, HH);
    transconv_k<<<dim3(DD / 32, HH / 32, EE), dim3(32, 8)>>>(W2, w2h, HH, DD);

    gemm_hmma<DD, HH, 1><<<dim3(HH / NT, MAXROWS / BMT), 128, GEMM_SMEM>>>(
        ah, w1h, b1, nullptr);
    gemm_hmma<HH, DD, 2><<<dim3(DD / NT, MAXROWS / BMT), 128, GEMM_SMEM>>>(
        hh, w2h, b2, out);
}